// round 1
// baseline (speedup 1.0000x reference)
#include <cuda_runtime.h>
#include <math.h>
#include <cfloat>

#define BSZ 16
#define CC 256
#define TT 768
#define PP 12
#define NPATCH 64
#define FF 256
#define NH 4
#define HDIM 64

// float(np.sqrt(1.0 + 1e-5)) computed in double then rounded
#define SQ_1PEPS 1.0000049999875001f

// ---------------- scratch / precomputed params (device globals; no allocs) ----
static __device__ float g_xn[BSZ * CC * TT];          // BN0-normalized input
static __device__ float g_wq[FF], g_cq[FF], g_wk[FF], g_ck[FF], g_wv[FF], g_cv[FF];
static __device__ float g_A[NH], g_D[NH];             // per-head score scalars (scaled 1/8)
static __device__ float g_M4[FF * 4];                 // interleaved [g][h]
static __device__ float g_c0w2[FF * 2];               // interleaved [g][{c0, Wm2}]
static __device__ float g_bn1s[CC * PP], g_bn2s[CC * PP];

__device__ __forceinline__ float gelu_exact(float x) {
    return 0.5f * x * (1.0f + erff(x * 0.7071067811865475f));
}

// ---------------- precompute: rank-1 collapse of all weight matrices ---------
__global__ void prep_params(const float* __restrict__ Wq, const float* __restrict__ bq,
                            const float* __restrict__ Wk, const float* __restrict__ bk,
                            const float* __restrict__ Wv, const float* __restrict__ bv,
                            const float* __restrict__ We, const float* __restrict__ be,
                            const float* __restrict__ Wm1, const float* __restrict__ bm1,
                            const float* __restrict__ Wm2,
                            const float* __restrict__ g1, const float* __restrict__ g2) {
    int f = threadIdx.x;  // 256 threads
    float wq = 0, cq = 0, wk = 0, ck = 0, wv = 0, cv = 0;
    for (int j = 0; j < FF; j++) {
        float e = We[j], bb = be[j];
        float aq = Wq[f * FF + j], ak = Wk[f * FF + j], av = Wv[f * FF + j];
        wq += aq * e; cq += aq * bb;
        wk += ak * e; ck += ak * bb;
        wv += av * e; cv += av * bb;
    }
    cq += bq[f]; ck += bk[f]; cv += bv[f];
    g_wq[f] = wq; g_cq[f] = cq; g_wk[f] = wk; g_ck[f] = ck; g_wv[f] = wv; g_cv[f] = cv;
    __syncthreads();

    if (f < NH) {
        float A = 0, D = 0;
        for (int d = 0; d < HDIM; d++) {
            A += g_wq[f * HDIM + d] * g_wk[f * HDIM + d];
            D += g_cq[f * HDIM + d] * g_wk[f * HDIM + d];
        }
        g_A[f] = A * 0.125f;  // 1/sqrt(HD) = 1/8
        g_D[f] = D * 0.125f;
    }

    float c0 = bm1[f];
    for (int h = 0; h < NH; h++) {
        float m = 0;
        for (int d = 0; d < HDIM; d++) {
            int j = h * HDIM + d;
            float w = Wm1[f * FF + j];
            m  += w * g_wv[j];
            c0 += w * g_cv[j];
        }
        g_M4[f * 4 + h] = m;
    }
    g_c0w2[f * 2 + 0] = c0;
    g_c0w2[f * 2 + 1] = Wm2[f];

    for (int r = 0; r < PP; r++) {
        int j = f * PP + r;
        g_bn1s[j] = g1[j] / SQ_1PEPS;
        g_bn2s[j] = g2[j] / SQ_1PEPS;
    }
}

// ---------------- precompute: outer BatchNorm + emit patch 0 -----------------
__global__ void prep_xn(const float* __restrict__ x, const float* __restrict__ g0,
                        const float* __restrict__ b0, float* __restrict__ out) {
    int i = blockIdx.x * blockDim.x + threadIdx.x;
    if (i >= BSZ * CC * TT) return;
    int feat = i % (CC * TT);
    float v = x[i] * (g0[feat] / SQ_1PEPS) + b0[feat];
    g_xn[i] = v;
    if ((i % TT) < PP) out[i] = v;  // out0 = xp[0]
}

// ---------------- one scan step --------------------------------------------
// grid = 16 * 12 * 2 = 384 blocks (b, p, c-half), block = 256 threads
__global__ __launch_bounds__(256) void step_kernel(
        int s, float* __restrict__ out,
        const float* __restrict__ b1v, const float* __restrict__ b2v,
        const float* __restrict__ Wagg, const float* __restrict__ bagg,
        const float* __restrict__ bm2) {
    __shared__ float t_sh[CC];
    __shared__ float res_sh[CC];
    __shared__ __align__(16) float sM4[FF * 4];
    __shared__ __align__(8)  float sc0w2[FF * 2];
    __shared__ float sWagg[PP * PP];
    __shared__ float sbagg[PP];
    __shared__ float redv[8];
    __shared__ int   redi[8];
    __shared__ float topv[3], botv[3];
    __shared__ int sexi;

    int tid = threadIdx.x;
    int blk = blockIdx.x;
    int b = blk / 24;
    int rem = blk % 24;
    int p = rem >> 1;
    int half = rem & 1;

    for (int i = tid; i < FF * 4; i += 256) sM4[i] = g_M4[i];
    for (int i = tid; i < FF * 2; i += 256) sc0w2[i] = g_c0w2[i];
    if (tid < PP * PP) sWagg[tid] = Wagg[tid];
    if (tid < PP) sbagg[tid] = bagg[tid];
    __syncthreads();

    // ---- Phase A: agg + residual + BN2  (thread = channel c) ----
    int c = tid;
    size_t rowbase = ((size_t)b * CC + c) * TT;
    const float4* pr = (const float4*)(out + rowbase + (size_t)(s - 1) * PP);
    float4 p0 = pr[0], p1 = pr[1], p2 = pr[2];
    float pv[12] = {p0.x, p0.y, p0.z, p0.w, p1.x, p1.y, p1.z, p1.w, p2.x, p2.y, p2.z, p2.w};
    float acc = sbagg[p];
    #pragma unroll
    for (int j = 0; j < PP; j++) {
        int fi = c * PP + j;
        float v = pv[j] * g_bn1s[fi] + b1v[fi];
        acc += sWagg[p * PP + j] * v;
    }
    float res = gelu_exact(acc) + g_xn[rowbase + (size_t)s * PP + p];
    int fi2 = c * PP + p;
    float t_c = res * g_bn2s[fi2] + b2v[fi2];
    t_sh[c] = t_c;
    res_sh[c] = res;
    __syncthreads();

    // ---- Phase B: block-wide top-3 and bottom-3 of t over c ----
    bool ex = false;
    for (int r = 0; r < 3; r++) {
        float v = ex ? -FLT_MAX : t_c;
        int idx = tid;
        #pragma unroll
        for (int off = 16; off; off >>= 1) {
            float ov = __shfl_down_sync(0xffffffffu, v, off);
            int   oi = __shfl_down_sync(0xffffffffu, idx, off);
            if (ov > v || (ov == v && oi < idx)) { v = ov; idx = oi; }
        }
        if ((tid & 31) == 0) { redv[tid >> 5] = v; redi[tid >> 5] = idx; }
        __syncthreads();
        if (tid == 0) {
            float bv = redv[0]; int bi = redi[0];
            #pragma unroll
            for (int w = 1; w < 8; w++)
                if (redv[w] > bv || (redv[w] == bv && redi[w] < bi)) { bv = redv[w]; bi = redi[w]; }
            topv[r] = bv; sexi = bi;
        }
        __syncthreads();
        if (tid == sexi) ex = true;
    }
    __syncthreads();
    ex = false;
    for (int r = 0; r < 3; r++) {
        float v = ex ? FLT_MAX : t_c;
        int idx = tid;
        #pragma unroll
        for (int off = 16; off; off >>= 1) {
            float ov = __shfl_down_sync(0xffffffffu, v, off);
            int   oi = __shfl_down_sync(0xffffffffu, idx, off);
            if (ov < v || (ov == v && oi < idx)) { v = ov; idx = oi; }
        }
        if ((tid & 31) == 0) { redv[tid >> 5] = v; redi[tid >> 5] = idx; }
        __syncthreads();
        if (tid == 0) {
            float bv = redv[0]; int bi = redi[0];
            #pragma unroll
            for (int w = 1; w < 8; w++)
                if (redv[w] < bv || (redv[w] == bv && redi[w] < bi)) { bv = redv[w]; bi = redi[w]; }
            botv[r] = bv; sexi = bi;
        }
        __syncthreads();
        if (tid == sexi) ex = true;
    }
    __syncthreads();

    float tv0 = topv[0], tv1 = topv[1], tv2 = topv[2];
    float bu0 = botv[0], bu1 = botv[1], bu2 = botv[2];
    float ts0 = t_sh[0], ts1 = t_sh[1], ts2 = t_sh[2];

    // ---- Phase C: 3-element softmax per (row, head) -> s1[4] ----
    // This block's half handles rows [half*128, half*128+128); 2 threads/row.
    int c2 = half * 128 + (tid >> 1);
    int part = tid & 1;
    float tc2 = t_sh[c2];
    float s1v[4];
    #pragma unroll
    for (int h = 0; h < NH; h++) {
        float coef = g_A[h] * tc2 + g_D[h];
        float a, bb, cc2;
        if (coef > 0.f)      { a = tv0; bb = tv1; cc2 = tv2; }
        else if (coef < 0.f) { a = bu0; bb = bu1; cc2 = bu2; }
        else                 { a = ts0; bb = ts1; cc2 = ts2; }  // ties -> first 3 indices
        float m  = coef * a;  // max of the 3 selected scores
        float e0 = __expf(coef * a - m);
        float e1 = __expf(coef * bb - m);
        float e2 = __expf(coef * cc2 - m);
        s1v[h] = (e0 * a + e1 * bb + e2 * cc2) / (e0 + e1 + e2);
    }

    // ---- Phase D: msg MLP: z = sum_g Wm2[g]*gelu(M[g,:]@s1 + c0[g]) ----
    float z = 0.f;
    #pragma unroll 4
    for (int k = 0; k < 128; k++) {
        int g = (k << 1) | part;  // even/odd split between partner threads
        float4 m4 = *(const float4*)&sM4[g * 4];
        float2 cw = *(const float2*)&sc0w2[g * 2];
        float y = cw.x + m4.x * s1v[0] + m4.y * s1v[1] + m4.z * s1v[2] + m4.w * s1v[3];
        z += cw.y * gelu_exact(y);
    }
    z += __shfl_xor_sync(0xffffffffu, z, 1);
    if (part == 0) {
        float nv = res_sh[c2] + 0.5f * (z + bm2[0]);
        out[((size_t)b * CC + c2) * TT + (size_t)s * PP + p] = nv;
    }
}

// ---------------- launch ----------------------------------------------------
extern "C" void kernel_launch(void* const* d_in, const int* in_sizes, int n_in,
                              void* d_out, int out_size) {
    const float* x    = (const float*)d_in[0];
    const float* g0   = (const float*)d_in[1];
    const float* b0   = (const float*)d_in[2];
    const float* g1   = (const float*)d_in[3];
    const float* b1   = (const float*)d_in[4];
    const float* g2   = (const float*)d_in[5];
    const float* b2   = (const float*)d_in[6];
    const float* Wagg = (const float*)d_in[7];
    const float* bagg = (const float*)d_in[8];
    const float* We   = (const float*)d_in[9];
    const float* be   = (const float*)d_in[10];
    const float* Wq   = (const float*)d_in[11];
    const float* bq   = (const float*)d_in[12];
    const float* Wk   = (const float*)d_in[13];
    const float* bk   = (const float*)d_in[14];
    const float* Wv   = (const float*)d_in[15];
    const float* bv   = (const float*)d_in[16];
    const float* Wm1  = (const float*)d_in[17];
    const float* bm1  = (const float*)d_in[18];
    const float* Wm2  = (const float*)d_in[19];
    const float* bm2  = (const float*)d_in[20];
    float* out = (float*)d_out;

    prep_params<<<1, 256>>>(Wq, bq, Wk, bk, Wv, bv, We, be, Wm1, bm1, Wm2, g1, g2);
    int n = BSZ * CC * TT;
    prep_xn<<<(n + 255) / 256, 256>>>(x, g0, b0, out);
    for (int s = 1; s < NPATCH; s++) {
        step_kernel<<<384, 256>>>(s, out, b1, b2, Wagg, bagg, bm2);
    }
}

// round 2
// speedup vs baseline: 1.1894x; 1.1894x over previous
#include <cuda_runtime.h>
#include <math.h>
#include <cfloat>

#define BSZ 16
#define CC 256
#define TT 768
#define PP 12
#define NPATCH 64
#define FF 256
#define NH 4
#define HDIM 64

#define SQ_1PEPS 1.0000049999875001f

typedef unsigned long long ull;

// ---------------- device scratch (no allocs) --------------------------------
static __device__ float g_xn[BSZ * CC * TT];
static __device__ float g_wq[FF], g_cq[FF], g_wk[FF], g_ck[FF], g_wv[FF], g_cv[FF];
static __device__ float g_A[NH], g_D[NH];
static __device__ float g_M4[FF * 4];          // [g][h]
static __device__ float g_c0[FF], g_w2s[FF];
static __device__ ulonglong2 g_Mau2[128], g_Mbu2[128], g_cwu2[128];
static __device__ float g_Wp[PP * CC * PP];    // [p][c][j] : Wagg[p][j]*bn1scale[c][j]
static __device__ float g_cst1[PP * CC];       // [p][c]
static __device__ float g_bn2s[CC * PP];

// ---------------- f32x2 packed helpers --------------------------------------
__device__ __forceinline__ ull pk(float a, float b) {
    ull r; asm("mov.b64 %0,{%1,%2};" : "=l"(r) : "f"(a), "f"(b)); return r;
}
__device__ __forceinline__ float2 upk(ull v) {
    float2 r; asm("mov.b64 {%0,%1},%2;" : "=f"(r.x), "=f"(r.y) : "l"(v)); return r;
}
__device__ __forceinline__ ull fma2(ull a, ull b, ull c) {
    ull d; asm("fma.rn.f32x2 %0,%1,%2,%3;" : "=l"(d) : "l"(a), "l"(b), "l"(c)); return d;
}
__device__ __forceinline__ ull mul2(ull a, ull b) {
    ull d; asm("mul.rn.f32x2 %0,%1,%2;" : "=l"(d) : "l"(a), "l"(b)); return d;
}
__device__ __forceinline__ float rcpa(float x) {
    float r; asm("rcp.approx.f32 %0,%1;" : "=f"(r) : "f"(x)); return r;
}
__device__ __forceinline__ float ex2a(float x) {
    float r; asm("ex2.approx.f32 %0,%1;" : "=f"(r) : "f"(x)); return r;
}

// Packed exact-ish GELU: 0.5y(1+erf(y/sqrt2)), erf via A&S 7.1.26 (|err|<=1.5e-7)
__device__ __forceinline__ ull gelu2f(ull y2) {
    const ull MASK = 0x7FFFFFFF7FFFFFFFULL;
    ull u2  = mul2(y2, pk(0.7071067811865475f, 0.7071067811865475f));
    ull au2 = u2 & MASK;
    ull d2  = fma2(au2, pk(0.3275911f, 0.3275911f), pk(1.f, 1.f));
    float2 dd = upk(d2);
    ull t2 = pk(rcpa(dd.x), rcpa(dd.y));
    // p2 = -P(t) (Horner with negated A&S coefficients)
    ull p2 = fma2(t2, pk(-1.061405429f, -1.061405429f), pk(1.453152027f, 1.453152027f));
    p2 = fma2(p2, t2, pk(-1.421413741f, -1.421413741f));
    p2 = fma2(p2, t2, pk(0.284496736f, 0.284496736f));
    p2 = fma2(p2, t2, pk(-0.254829592f, -0.254829592f));
    p2 = mul2(p2, t2);
    ull s2 = mul2(u2, u2);
    ull ea = mul2(s2, pk(-1.4426950408889634f, -1.4426950408889634f));
    float2 ee = upk(ea);
    ull e2 = pk(ex2a(ee.x), ex2a(ee.y));
    ull E2 = fma2(p2, e2, pk(1.f, 1.f));         // 1 - P(t)e^{-u^2} = erf(|u|)
    ull hy2 = mul2(y2, pk(0.5f, 0.5f));
    ull ahy2 = hy2 & MASK;
    return fma2(ahy2, E2, hy2);                   // 0.5y + 0.5|y|erf(|u|)
}

// merge two sorted-desc triples -> top-3 sorted desc in (x0,x1,x2)
__device__ __forceinline__ void merge3(float& x0, float& x1, float& x2,
                                       float y0, float y1, float y2) {
    if (y0 > x0) { float t;
        t = x0; x0 = y0; y0 = t;
        t = x1; x1 = y1; y1 = t;
        t = x2; x2 = y2; y2 = t;
    }
    float mn  = fminf(x1, y0);
    float alt = (x1 >= y0) ? x2 : y1;
    x1 = fmaxf(x1, y0);
    x2 = fmaxf(mn, alt);
}

// ---------------- precompute ------------------------------------------------
__global__ void prep_params(const float* __restrict__ Wq, const float* __restrict__ bq,
                            const float* __restrict__ Wk, const float* __restrict__ bk,
                            const float* __restrict__ Wv, const float* __restrict__ bv,
                            const float* __restrict__ We, const float* __restrict__ be,
                            const float* __restrict__ Wm1, const float* __restrict__ bm1,
                            const float* __restrict__ Wm2,
                            const float* __restrict__ g1, const float* __restrict__ b1,
                            const float* __restrict__ g2,
                            const float* __restrict__ Wagg, const float* __restrict__ bagg) {
    int f = threadIdx.x;  // 256 threads
    float wq = 0, cq = 0, wk = 0, ck = 0, wv = 0, cv = 0;
    for (int j = 0; j < FF; j++) {
        float e = We[j], bb = be[j];
        float aq = Wq[f * FF + j], ak = Wk[f * FF + j], av = Wv[f * FF + j];
        wq += aq * e; cq += aq * bb;
        wk += ak * e; ck += ak * bb;
        wv += av * e; cv += av * bb;
    }
    cq += bq[f]; ck += bk[f]; cv += bv[f];
    g_wq[f] = wq; g_cq[f] = cq; g_wk[f] = wk; g_ck[f] = ck; g_wv[f] = wv; g_cv[f] = cv;
    __syncthreads();

    if (f < NH) {
        float A = 0, D = 0;
        for (int d = 0; d < HDIM; d++) {
            A += g_wq[f * HDIM + d] * g_wk[f * HDIM + d];
            D += g_cq[f * HDIM + d] * g_wk[f * HDIM + d];
        }
        g_A[f] = A * 0.125f;
        g_D[f] = D * 0.125f;
    }

    float c0 = bm1[f];
    for (int h = 0; h < NH; h++) {
        float m = 0;
        for (int d = 0; d < HDIM; d++) {
            int j = h * HDIM + d;
            float w = Wm1[f * FF + j];
            m  += w * g_wv[j];
            c0 += w * g_cv[j];
        }
        g_M4[f * 4 + h] = m;
    }
    g_c0[f]  = c0;
    g_w2s[f] = Wm2[f];

    for (int r = 0; r < PP; r++)
        g_bn2s[f * PP + r] = g2[f * PP + r] / SQ_1PEPS;

    for (int p = 0; p < PP; p++) {
        float cst = bagg[p];
        for (int j = 0; j < PP; j++) {
            float wa = Wagg[p * PP + j];
            g_Wp[((p << 8) + f) * PP + j] = wa * (g1[f * PP + j] / SQ_1PEPS);
            cst += wa * b1[f * PP + j];
        }
        g_cst1[(p << 8) + f] = cst;
    }
    __syncthreads();

    if (f < 128) {
        int j = f;
        g_Mau2[j].x = pk(g_M4[(2 * j) * 4 + 0], g_M4[(2 * j + 1) * 4 + 0]);
        g_Mau2[j].y = pk(g_M4[(2 * j) * 4 + 1], g_M4[(2 * j + 1) * 4 + 1]);
        g_Mbu2[j].x = pk(g_M4[(2 * j) * 4 + 2], g_M4[(2 * j + 1) * 4 + 2]);
        g_Mbu2[j].y = pk(g_M4[(2 * j) * 4 + 3], g_M4[(2 * j + 1) * 4 + 3]);
        g_cwu2[j].x = pk(g_c0[2 * j], g_c0[2 * j + 1]);
        g_cwu2[j].y = pk(g_w2s[2 * j], g_w2s[2 * j + 1]);
    }
}

__global__ void prep_xn(const float* __restrict__ x, const float* __restrict__ g0,
                        const float* __restrict__ b0, float* __restrict__ out) {
    int i = blockIdx.x * blockDim.x + threadIdx.x;
    if (i >= BSZ * CC * TT) return;
    int feat = i % (CC * TT);
    float v = x[i] * (g0[feat] / SQ_1PEPS) + b0[feat];
    g_xn[i] = v;
    if ((i % TT) < PP) out[i] = v;
}

// ---------------- one scan step ---------------------------------------------
// grid = 16*12*4 = 768 blocks (b, p, quarter), 128 threads
__global__ void __launch_bounds__(128) step_kernel(
        int s, float* __restrict__ out,
        const float* __restrict__ b2v, const float* __restrict__ bm2) {
    __shared__ float t_sh[CC];
    __shared__ float res_sh[CC];
    __shared__ ulonglong2 sMa[128], sMb[128], scw[128];
    __shared__ float smB[4][6];

    int tid = threadIdx.x;
    int blk = blockIdx.x;
    int b = blk / 48;
    int rem = blk % 48;
    int p = rem >> 2;
    int q = rem & 3;

    sMa[tid] = g_Mau2[tid];
    sMb[tid] = g_Mbu2[tid];
    scw[tid] = g_cwu2[tid];

    // ---- Phase A: agg(+BN1 folded) + gelu + residual + BN2 (2 channels/thr)
    float accv[2], xnv[2];
    #pragma unroll
    for (int hh = 0; hh < 2; hh++) {
        int c = tid + hh * 128;
        size_t rowbase = ((size_t)b * CC + c) * TT;
        const float4* wp = (const float4*)&g_Wp[((p << 8) + c) * PP];
        const float4* pr = (const float4*)(out + rowbase + (size_t)(s - 1) * PP);
        float4 w0 = wp[0], w1 = wp[1], w2_ = wp[2];
        float4 p0 = pr[0], p1 = pr[1], p2_ = pr[2];
        float acc = g_cst1[(p << 8) + c];
        acc += w0.x * p0.x + w0.y * p0.y + w0.z * p0.z + w0.w * p0.w
             + w1.x * p1.x + w1.y * p1.y + w1.z * p1.z + w1.w * p1.w
             + w2_.x * p2_.x + w2_.y * p2_.y + w2_.z * p2_.z + w2_.w * p2_.w;
        accv[hh] = acc;
        xnv[hh] = g_xn[rowbase + (size_t)s * PP + p];
    }
    float2 gg = upk(gelu2f(pk(accv[0], accv[1])));
    float res0 = gg.x + xnv[0], res1 = gg.y + xnv[1];
    float t0 = res0 * g_bn2s[tid * PP + p] + b2v[tid * PP + p];
    float t1 = res1 * g_bn2s[(tid + 128) * PP + p] + b2v[(tid + 128) * PP + p];
    t_sh[tid] = t0;  t_sh[tid + 128] = t1;
    res_sh[tid] = res0; res_sh[tid + 128] = res1;

    // ---- Phase B: top-3 / bottom-3 values over c (merge network) ----
    float a0 = fmaxf(t0, t1), a1 = fminf(t0, t1), a2 = -FLT_MAX;
    float n0 = fmaxf(-t0, -t1), n1 = fminf(-t0, -t1), n2 = -FLT_MAX;
    #pragma unroll
    for (int off = 16; off; off >>= 1) {
        float y0 = __shfl_xor_sync(0xffffffffu, a0, off);
        float y1 = __shfl_xor_sync(0xffffffffu, a1, off);
        float y2 = __shfl_xor_sync(0xffffffffu, a2, off);
        merge3(a0, a1, a2, y0, y1, y2);
        y0 = __shfl_xor_sync(0xffffffffu, n0, off);
        y1 = __shfl_xor_sync(0xffffffffu, n1, off);
        y2 = __shfl_xor_sync(0xffffffffu, n2, off);
        merge3(n0, n1, n2, y0, y1, y2);
    }
    int wid = tid >> 5, lid = tid & 31;
    if (lid == 0) {
        smB[wid][0] = a0; smB[wid][1] = a1; smB[wid][2] = a2;
        smB[wid][3] = n0; smB[wid][4] = n1; smB[wid][5] = n2;
    }
    __syncthreads();
    a0 = smB[0][0]; a1 = smB[0][1]; a2 = smB[0][2];
    n0 = smB[0][3]; n1 = smB[0][4]; n2 = smB[0][5];
    #pragma unroll
    for (int w = 1; w < 4; w++) {
        merge3(a0, a1, a2, smB[w][0], smB[w][1], smB[w][2]);
        merge3(n0, n1, n2, smB[w][3], smB[w][4], smB[w][5]);
    }
    float tv0 = a0, tv1 = a1, tv2 = a2;
    float bu0 = -n0, bu1 = -n1, bu2 = -n2;
    float ts0 = t_sh[0], ts1 = t_sh[1], ts2 = t_sh[2];

    // ---- Phase C: 3-element softmax per (row, head) ----
    int c2 = (q << 6) + (tid >> 1);
    int part = tid & 1;
    float tc2 = t_sh[c2];
    ull s1x2[NH];
    #pragma unroll
    for (int h = 0; h < NH; h++) {
        float coef = g_A[h] * tc2 + g_D[h];
        float aa, bb, cc;
        if (coef > 0.f)      { aa = tv0; bb = tv1; cc = tv2; }
        else if (coef < 0.f) { aa = bu0; bb = bu1; cc = bu2; }
        else                 { aa = ts0; bb = ts1; cc = ts2; }
        float e1 = __expf(coef * (bb - aa));
        float e2 = __expf(coef * (cc - aa));
        float s1 = __fdividef(aa + e1 * bb + e2 * cc, 1.f + e1 + e2);
        s1x2[h] = pk(s1, s1);
    }

    // ---- Phase D: z = sum_g w2[g]*gelu(c0[g] + M[g,:]@s1), packed 2 g/iter
    ull z2 = pk(0.f, 0.f);
    int base = part << 6;
    #pragma unroll 4
    for (int j = 0; j < 64; j++) {
        ulonglong2 ma = sMa[base + j];
        ulonglong2 mb = sMb[base + j];
        ulonglong2 cw = scw[base + j];
        ull y2 = fma2(ma.x, s1x2[0], cw.x);
        y2 = fma2(ma.y, s1x2[1], y2);
        y2 = fma2(mb.x, s1x2[2], y2);
        y2 = fma2(mb.y, s1x2[3], y2);
        z2 = fma2(cw.y, gelu2f(y2), z2);
    }
    float2 zz = upk(z2);
    float z = zz.x + zz.y;
    z += __shfl_xor_sync(0xffffffffu, z, 1);
    if (part == 0) {
        out[((size_t)b * CC + c2) * TT + (size_t)s * PP + p] =
            res_sh[c2] + 0.5f * (z + bm2[0]);
    }
}

// ---------------- launch ----------------------------------------------------
extern "C" void kernel_launch(void* const* d_in, const int* in_sizes, int n_in,
                              void* d_out, int out_size) {
    const float* x    = (const float*)d_in[0];
    const float* g0   = (const float*)d_in[1];
    const float* b0   = (const float*)d_in[2];
    const float* g1   = (const float*)d_in[3];
    const float* b1   = (const float*)d_in[4];
    const float* g2   = (const float*)d_in[5];
    const float* b2   = (const float*)d_in[6];
    const float* Wagg = (const float*)d_in[7];
    const float* bagg = (const float*)d_in[8];
    const float* We   = (const float*)d_in[9];
    const float* be   = (const float*)d_in[10];
    const float* Wq   = (const float*)d_in[11];
    const float* bq   = (const float*)d_in[12];
    const float* Wk   = (const float*)d_in[13];
    const float* bk   = (const float*)d_in[14];
    const float* Wv   = (const float*)d_in[15];
    const float* bv   = (const float*)d_in[16];
    const float* Wm1  = (const float*)d_in[17];
    const float* bm1  = (const float*)d_in[18];
    const float* Wm2  = (const float*)d_in[19];
    const float* bm2  = (const float*)d_in[20];
    float* out = (float*)d_out;

    prep_params<<<1, 256>>>(Wq, bq, Wk, bk, Wv, bv, We, be, Wm1, bm1, Wm2,
                            g1, b1, g2, Wagg, bagg);
    int n = BSZ * CC * TT;
    prep_xn<<<(n + 255) / 256, 256>>>(x, g0, b0, out);
    for (int s = 1; s < NPATCH; s++) {
        step_kernel<<<768, 128>>>(s, out, b2, bm2);
    }
}